// round 1
// baseline (speedup 1.0000x reference)
#include <cuda_runtime.h>
#include <math.h>

#define NS    4096        // num samples per view
#define NTOT  8192        // total rows (2 views)
#define DIM   512
#define INV_T 2.0f        // 1 / temperature (0.5)
#define BM 128
#define BN 128
#define BK 16

// Scratch (allocation-free rule: __device__ globals)
__device__ float g_inv_norm[NTOT];
__device__ float g_row_exp[NTOT];   // sum of exp(s) over negatives, per row
__device__ float g_row_sim[NTOT];   // sum of s over negatives, per row
__device__ float g_spos[NTOT];      // s at the positive pair, per row

__device__ __forceinline__ const float* row_ptr(const float* x1, const float* x2, int r) {
    return (r < NS) ? (x1 + (size_t)r * DIM) : (x2 + (size_t)(r - NS) * DIM);
}

// Kernel 1: per-row inverse norms + zero the accumulators (must re-zero every
// graph replay).
__global__ void prep_kernel(const float* __restrict__ x1, const float* __restrict__ x2) {
    int row  = blockIdx.x * 8 + (threadIdx.x >> 5);  // 8 warps per 256-thread block
    int lane = threadIdx.x & 31;
    if (row >= NTOT) return;
    const float* xr = row_ptr(x1, x2, row);
    float s = 0.f;
    #pragma unroll
    for (int c = 0; c < DIM / 32; c++) {
        float v = xr[lane + 32 * c];
        s = fmaf(v, v, s);
    }
    #pragma unroll
    for (int o = 16; o; o >>= 1) s += __shfl_xor_sync(0xffffffffu, s, o);
    if (lane == 0) {
        g_inv_norm[row] = rsqrtf(s);
        g_row_exp[row]  = 0.f;
        g_row_sim[row]  = 0.f;
        g_spos[row]     = 0.f;
    }
}

// Kernel 2: fused X @ X^T tile GEMM + masked exp epilogue.
// 128x128 tile per 256-thread block, 8x8 per thread (split 4+4 strided to keep
// shared loads conflict-free).
__global__ __launch_bounds__(256, 2)
void sim_kernel(const float* __restrict__ x1, const float* __restrict__ x2) {
    __shared__ float As[BK][BM];
    __shared__ float Bs[BK][BN];

    const int tid  = threadIdx.x;
    const int tx   = tid & 15;
    const int ty   = tid >> 4;
    const int row0 = blockIdx.y * BM;
    const int col0 = blockIdx.x * BN;

    // Global->shared load indices: 128 rows x 16 cols per tile, 2 float4 per thread
    const int lrow = tid >> 2;          // 0..63
    const int lcol = (tid & 3) << 2;    // 0,4,8,12

    const float* aptr0 = row_ptr(x1, x2, row0 + lrow)      + lcol;
    const float* aptr1 = row_ptr(x1, x2, row0 + lrow + 64) + lcol;
    const float* bptr0 = row_ptr(x1, x2, col0 + lrow)      + lcol;
    const float* bptr1 = row_ptr(x1, x2, col0 + lrow + 64) + lcol;

    float acc[8][8];
    #pragma unroll
    for (int m = 0; m < 8; m++)
        #pragma unroll
        for (int n = 0; n < 8; n++) acc[m][n] = 0.f;

    for (int k0 = 0; k0 < DIM; k0 += BK) {
        float4 a0 = *(const float4*)(aptr0 + k0);
        float4 a1 = *(const float4*)(aptr1 + k0);
        float4 b0 = *(const float4*)(bptr0 + k0);
        float4 b1 = *(const float4*)(bptr1 + k0);
        __syncthreads();   // previous iteration's compute done before overwrite
        As[lcol + 0][lrow] = a0.x; As[lcol + 1][lrow] = a0.y;
        As[lcol + 2][lrow] = a0.z; As[lcol + 3][lrow] = a0.w;
        As[lcol + 0][lrow + 64] = a1.x; As[lcol + 1][lrow + 64] = a1.y;
        As[lcol + 2][lrow + 64] = a1.z; As[lcol + 3][lrow + 64] = a1.w;
        Bs[lcol + 0][lrow] = b0.x; Bs[lcol + 1][lrow] = b0.y;
        Bs[lcol + 2][lrow] = b0.z; Bs[lcol + 3][lrow] = b0.w;
        Bs[lcol + 0][lrow + 64] = b1.x; Bs[lcol + 1][lrow + 64] = b1.y;
        Bs[lcol + 2][lrow + 64] = b1.z; Bs[lcol + 3][lrow + 64] = b1.w;
        __syncthreads();

        #pragma unroll
        for (int k = 0; k < BK; k++) {
            float4 af0 = *(const float4*)&As[k][ty * 4];
            float4 af1 = *(const float4*)&As[k][64 + ty * 4];
            float4 bf0 = *(const float4*)&Bs[k][tx * 4];
            float4 bf1 = *(const float4*)&Bs[k][64 + tx * 4];
            float a[8] = {af0.x, af0.y, af0.z, af0.w, af1.x, af1.y, af1.z, af1.w};
            float b[8] = {bf0.x, bf0.y, bf0.z, bf0.w, bf1.x, bf1.y, bf1.z, bf1.w};
            #pragma unroll
            for (int m = 0; m < 8; m++)
                #pragma unroll
                for (int n = 0; n < 8; n++)
                    acc[m][n] = fmaf(a[m], b[n], acc[m][n]);
        }
    }

    // ---- Epilogue: scale to s = sim/t, mask, exp, per-row partial sums ----
    int gr[8], gc[8];
    #pragma unroll
    for (int m = 0; m < 4; m++) {
        gr[m]     = row0 + ty * 4 + m;
        gr[m + 4] = row0 + 64 + ty * 4 + m;
    }
    #pragma unroll
    for (int n = 0; n < 4; n++) {
        gc[n]     = col0 + tx * 4 + n;
        gc[n + 4] = col0 + 64 + tx * 4 + n;
    }
    float invi[8], invj[8];
    #pragma unroll
    for (int m = 0; m < 8; m++) invi[m] = g_inv_norm[gr[m]] * INV_T;
    #pragma unroll
    for (int n = 0; n < 8; n++) invj[n] = g_inv_norm[gc[n]];

    float texp[8], tsim[8];
    #pragma unroll
    for (int m = 0; m < 8; m++) { texp[m] = 0.f; tsim[m] = 0.f; }

    #pragma unroll
    for (int m = 0; m < 8; m++) {
        const int i     = gr[m];
        const int isamp = i & (NS - 1);
        #pragma unroll
        for (int n = 0; n < 8; n++) {
            const int j = gc[n];
            float s = acc[m][n] * invi[m] * invj[n];
            if ((j & (NS - 1)) == isamp) {
                if (i != j) g_spos[i] = s;   // unique writer per i
            } else {
                texp[m] += __expf(s);
                tsim[m] += s;
            }
        }
    }

    // Reduce across the 16 tx-lanes (contiguous within the warp)
    #pragma unroll
    for (int m = 0; m < 8; m++) {
        #pragma unroll
        for (int o = 8; o; o >>= 1) {
            texp[m] += __shfl_xor_sync(0xffffffffu, texp[m], o);
            tsim[m] += __shfl_xor_sync(0xffffffffu, tsim[m], o);
        }
    }
    if (tx == 0) {
        #pragma unroll
        for (int m = 0; m < 8; m++) {
            atomicAdd(&g_row_exp[gr[m]], texp[m]);
            atomicAdd(&g_row_sim[gr[m]], tsim[m]);
        }
    }
}

// Kernel 3: final 3-scalar reduction.
__global__ void finalize_kernel(float* __restrict__ out) {
    __shared__ float red[96];
    int tid = threadIdx.x;
    float l = 0.f, p = 0.f, nsum = 0.f;
    for (int i = tid; i < NTOT; i += 256) {
        float sp    = g_spos[i];
        float denom = __expf(sp) + g_row_exp[i] + 2.0f;  // +2 = exp(0) at the 2 masked entries
        l    += logf(denom) - sp;
        p    += sp;
        nsum += g_row_sim[i];
    }
    #pragma unroll
    for (int o = 16; o; o >>= 1) {
        l    += __shfl_xor_sync(0xffffffffu, l, o);
        p    += __shfl_xor_sync(0xffffffffu, p, o);
        nsum += __shfl_xor_sync(0xffffffffu, nsum, o);
    }
    int w = tid >> 5, lane = tid & 31;
    if (lane == 0) { red[w] = l; red[32 + w] = p; red[64 + w] = nsum; }
    __syncthreads();
    if (tid == 0) {
        float L = 0.f, P = 0.f, NN = 0.f;
        for (int w2 = 0; w2 < 8; w2++) { L += red[w2]; P += red[32 + w2]; NN += red[64 + w2]; }
        out[0] = L / (float)NTOT;
        out[1] = P / (float)NTOT;
        out[2] = NN / (float)((double)NTOT * (double)NTOT - 2.0 * (double)NTOT);
    }
}

extern "C" void kernel_launch(void* const* d_in, const int* in_sizes, int n_in,
                              void* d_out, int out_size) {
    const float* x1 = (const float*)d_in[0];
    const float* x2 = (const float*)d_in[1];
    prep_kernel<<<NTOT / 8, 256>>>(x1, x2);
    sim_kernel<<<dim3(NTOT / BN, NTOT / BM), 256>>>(x1, x2);
    finalize_kernel<<<1, 256>>>((float*)d_out);
}

// round 3
// speedup vs baseline: 5.2492x; 5.2492x over previous
#include <cuda_runtime.h>
#include <cuda_bf16.h>
#include <cstdint>
#include <math.h>

#define NS    4096
#define NTOT  8192
#define DIM   512
#define BM    128
#define BN    128
#define BK    32
#define NKC   (DIM / BK)      // 16 k-chunks
#define SQRT2F 1.41421356237f

// ---------------- scratch (__device__ globals; no allocation allowed) -------
__device__ __align__(16) __nv_bfloat16 g_Y[NTOT * DIM];  // normalized * sqrt(2)
__device__ float g_inv_norm[NTOT];
__device__ float g_row_exp[NTOT];
__device__ float g_row_sim[NTOT];
__device__ float g_spos[NTOT];

// ---------------- PTX helpers (all baseline PTX, no sm_103a features) -------
__device__ __forceinline__ uint32_t smem_u32(const void* p) {
    uint32_t a;
    asm("{ .reg .u64 t; cvta.to.shared.u64 t, %1; cvt.u32.u64 %0, t; }" : "=r"(a) : "l"(p));
    return a;
}
__device__ __forceinline__ void cp16(uint32_t dst, const void* src) {
    asm volatile("cp.async.cg.shared.global [%0], [%1], 16;" :: "r"(dst), "l"(src) : "memory");
}
__device__ __forceinline__ void ldm_x4(uint32_t* r, uint32_t addr) {
    asm volatile("ldmatrix.sync.aligned.m8n8.x4.shared.b16 {%0,%1,%2,%3}, [%4];"
                 : "=r"(r[0]), "=r"(r[1]), "=r"(r[2]), "=r"(r[3]) : "r"(addr));
}
__device__ __forceinline__ void mma16816(float* d, const uint32_t* a, const uint32_t* b) {
    asm volatile(
        "mma.sync.aligned.m16n8k16.row.col.f32.bf16.bf16.f32 "
        "{%0,%1,%2,%3}, {%4,%5,%6,%7}, {%8,%9}, {%0,%1,%2,%3};"
        : "+f"(d[0]), "+f"(d[1]), "+f"(d[2]), "+f"(d[3])
        : "r"(a[0]), "r"(a[1]), "r"(a[2]), "r"(a[3]), "r"(b[0]), "r"(b[1]));
}

// Swizzled smem offset: row r (0..127) of 64B (4x16B chunks), chunk c (0..3).
// bank(r,c) = (16r + 4(c ^ ((r>>1)&3))) mod 32 -> distinct across any 8
// consecutive rows at fixed c => conflict-free ldmatrix phases.
__device__ __forceinline__ uint32_t swz(int r, int c) {
    return (uint32_t)(r * 64 + ((c ^ ((r >> 1) & 3)) << 4));
}

// ---------------- kernel 1: norms + bf16 normalized copy + zero accums ------
__device__ __forceinline__ const float* row_ptr(const float* x1, const float* x2, int r) {
    return (r < NS) ? (x1 + (size_t)r * DIM) : (x2 + (size_t)(r - NS) * DIM);
}

__global__ void prep_kernel(const float* __restrict__ x1, const float* __restrict__ x2) {
    int row  = blockIdx.x * 8 + (threadIdx.x >> 5);
    int lane = threadIdx.x & 31;
    if (row >= NTOT) return;
    const float* xr = row_ptr(x1, x2, row);
    float v[DIM / 32];
    float s = 0.f;
    #pragma unroll
    for (int c = 0; c < DIM / 32; c++) {
        v[c] = xr[lane + 32 * c];
        s = fmaf(v[c], v[c], s);
    }
    #pragma unroll
    for (int o = 16; o; o >>= 1) s += __shfl_xor_sync(0xffffffffu, s, o);
    float inv = rsqrtf(s);
    if (lane == 0) {
        g_inv_norm[row] = inv;
        g_row_exp[row]  = 0.f;
        g_row_sim[row]  = 0.f;
    }
    float scale = inv * SQRT2F;
    __nv_bfloat16* yr = g_Y + (size_t)row * DIM;
    #pragma unroll
    for (int c = 0; c < DIM / 32; c++)
        yr[lane + 32 * c] = __float2bfloat16(v[c] * scale);
}

// ---------------- kernel 2: exact fp32 positive-pair similarities -----------
__global__ void pos_kernel(const float* __restrict__ x1, const float* __restrict__ x2) {
    int row  = blockIdx.x * 8 + (threadIdx.x >> 5);
    int lane = threadIdx.x & 31;
    if (row >= NS) return;
    const float* a = x1 + (size_t)row * DIM;
    const float* b = x2 + (size_t)row * DIM;
    float s = 0.f;
    #pragma unroll
    for (int c = 0; c < DIM / 32; c++)
        s = fmaf(a[lane + 32 * c], b[lane + 32 * c], s);
    #pragma unroll
    for (int o = 16; o; o >>= 1) s += __shfl_xor_sync(0xffffffffu, s, o);
    if (lane == 0) {
        float sp = 2.0f * s * g_inv_norm[row] * g_inv_norm[row + NS];
        g_spos[row]      = sp;
        g_spos[row + NS] = sp;
    }
}

// ---------------- kernel 3: HMMA (mma.sync bf16) GEMM + masked exp epilogue -
// 128x128 tile, 8 warps as 4(m) x 2(n): warp tile 32m x 64n.
#define STAGE_BYTES 16384   // A 8KB + B 8KB

__global__ __launch_bounds__(256, 2) void gemm_kernel() {
    __shared__ __align__(128) char smem[2 * STAGE_BYTES];
    const uint32_t sb = smem_u32(smem);
    const int tid  = threadIdx.x, lane = tid & 31, wid = tid >> 5;
    const int wm   = wid & 3, wn = wid >> 2;
    const int row0 = blockIdx.y * BM, col0 = blockIdx.x * BN;

    // Global->shared: each thread moves 2x16B of A and 2x16B of B per stage.
    const int lr  = tid >> 1;          // row 0..127
    const int lc0 = (tid & 1) * 2;     // chunk 0 or 2
    const char* a_gsrc = (const char*)(g_Y + (size_t)(row0 + lr) * DIM) + lc0 * 16;
    const char* b_gsrc = (const char*)(g_Y + (size_t)(col0 + lr) * DIM) + lc0 * 16;

    float acc[2][8][4];
    #pragma unroll
    for (int mi = 0; mi < 2; mi++)
        #pragma unroll
        for (int ni = 0; ni < 8; ni++)
            #pragma unroll
            for (int c = 0; c < 4; c++) acc[mi][ni][c] = 0.f;

    const uint32_t adst0 = swz(lr, lc0), adst1 = swz(lr, lc0 + 1);

    // prologue: stage 0
    {
        uint32_t Ab = sb, Bb = sb + 8192;
        cp16(Ab + adst0, a_gsrc);
        cp16(Ab + adst1, a_gsrc + 16);
        cp16(Bb + adst0, b_gsrc);
        cp16(Bb + adst1, b_gsrc + 16);
        asm volatile("cp.async.commit_group;" ::: "memory");
    }

    for (int kc = 0; kc < NKC; kc++) {
        if (kc + 1 < NKC) {
            uint32_t Ab = sb + ((kc + 1) & 1) * STAGE_BYTES, Bb = Ab + 8192;
            const char* as = a_gsrc + (size_t)(kc + 1) * BK * 2;
            const char* bs = b_gsrc + (size_t)(kc + 1) * BK * 2;
            cp16(Ab + adst0, as);
            cp16(Ab + adst1, as + 16);
            cp16(Bb + adst0, bs);
            cp16(Bb + adst1, bs + 16);
            asm volatile("cp.async.commit_group;" ::: "memory");
            asm volatile("cp.async.wait_group 1;" ::: "memory");
        } else {
            asm volatile("cp.async.wait_group 0;" ::: "memory");
        }
        __syncthreads();

        const uint32_t Ab = sb + (kc & 1) * STAGE_BYTES, Bb = Ab + 8192;
        #pragma unroll
        for (int ks = 0; ks < 2; ks++) {
            // ldmatrix lane addressing: rows +8 for odd 8-lane group, k+8 for lanes>=16
            const int lrow = (lane & 7) + ((lane >> 3) & 1) * 8;
            const int lchk = ks * 2 + (lane >> 4);
            uint32_t a[2][4];
            #pragma unroll
            for (int mi = 0; mi < 2; mi++)
                ldm_x4(a[mi], Ab + swz(wm * 32 + mi * 16 + lrow, lchk));
            uint32_t b[8][2];
            #pragma unroll
            for (int np = 0; np < 4; np++) {
                uint32_t t[4];
                ldm_x4(t, Bb + swz(wn * 64 + np * 16 + lrow, lchk));
                b[np * 2][0]     = t[0]; b[np * 2][1]     = t[2];
                b[np * 2 + 1][0] = t[1]; b[np * 2 + 1][1] = t[3];
            }
            #pragma unroll
            for (int mi = 0; mi < 2; mi++)
                #pragma unroll
                for (int ni = 0; ni < 8; ni++)
                    mma16816(acc[mi][ni], a[mi], b[ni]);
        }
        __syncthreads();   // compute done before next iter overwrites this buffer
    }

    // ---- epilogue: mask, exp, per-row sums, quad-reduce, atomics ----
    const int rbase = row0 + wm * 32 + (lane >> 2);
    const int cbase = col0 + wn * 64 + 2 * (lane & 3);
    float rexp[2][2], rsim[2][2];
    #pragma unroll
    for (int mi = 0; mi < 2; mi++)
        #pragma unroll
        for (int h = 0; h < 2; h++) { rexp[mi][h] = 0.f; rsim[mi][h] = 0.f; }

    #pragma unroll
    for (int mi = 0; mi < 2; mi++) {
        #pragma unroll
        for (int c = 0; c < 4; c++) {
            const int h = c >> 1;
            const int i = rbase + mi * 16 + h * 8;
            #pragma unroll
            for (int ni = 0; ni < 8; ni++) {
                const int j = cbase + ni * 8 + (c & 1);
                float s = acc[mi][ni][c];
                if (((i ^ j) & (NS - 1)) != 0) {
                    rexp[mi][h] += __expf(s);
                    rsim[mi][h] += s;
                }
            }
        }
    }
    #pragma unroll
    for (int mi = 0; mi < 2; mi++)
        #pragma unroll
        for (int h = 0; h < 2; h++) {
            float e = rexp[mi][h], s = rsim[mi][h];
            e += __shfl_xor_sync(0xffffffffu, e, 1);
            e += __shfl_xor_sync(0xffffffffu, e, 2);
            s += __shfl_xor_sync(0xffffffffu, s, 1);
            s += __shfl_xor_sync(0xffffffffu, s, 2);
            if ((lane & 3) == 0) {
                const int i = rbase + mi * 16 + h * 8;
                atomicAdd(&g_row_exp[i], e);
                atomicAdd(&g_row_sim[i], s);
            }
        }
}

// ---------------- kernel 4: final 3-scalar reduction ------------------------
__global__ void finalize_kernel(float* __restrict__ out) {
    __shared__ float red[24];
    int tid = threadIdx.x;
    float l = 0.f, p = 0.f, nsum = 0.f;
    for (int i = tid; i < NTOT; i += 256) {
        float sp    = g_spos[i];
        float denom = __expf(sp) + g_row_exp[i] + 2.0f;  // +2 = exp(0) at 2 masked entries
        l    += logf(denom) - sp;
        p    += sp;
        nsum += g_row_sim[i];
    }
    #pragma unroll
    for (int o = 16; o; o >>= 1) {
        l    += __shfl_xor_sync(0xffffffffu, l, o);
        p    += __shfl_xor_sync(0xffffffffu, p, o);
        nsum += __shfl_xor_sync(0xffffffffu, nsum, o);
    }
    int w = tid >> 5, lane = tid & 31;
    if (lane == 0) { red[w] = l; red[8 + w] = p; red[16 + w] = nsum; }
    __syncthreads();
    if (tid == 0) {
        float L = 0.f, P = 0.f, NN = 0.f;
        for (int k = 0; k < 8; k++) { L += red[k]; P += red[8 + k]; NN += red[16 + k]; }
        out[0] = L / (float)NTOT;
        out[1] = P / (float)NTOT;
        out[2] = NN / (float)((double)NTOT * (double)NTOT - 2.0 * (double)NTOT);
    }
}

extern "C" void kernel_launch(void* const* d_in, const int* in_sizes, int n_in,
                              void* d_out, int out_size) {
    const float* x1 = (const float*)d_in[0];
    const float* x2 = (const float*)d_in[1];
    prep_kernel<<<NTOT / 8, 256>>>(x1, x2);
    pos_kernel<<<NS / 8, 256>>>(x1, x2);
    gemm_kernel<<<dim3(NTOT / BN, NTOT / BM), 256>>>();
    finalize_kernel<<<1, 256>>>((float*)d_out);
}